// round 12
// baseline (speedup 1.0000x reference)
#include <cuda_runtime.h>
#include <cuda_fp16.h>
#include <cstdint>

// Problem constants
#define BB 8
#define NN 2048
#define HH 4
#define DD 64
#define OUTC 256

// log2(e) / sqrt(D)
#define SCALE_LOG2E (1.4426950408889634f * 0.125f)

// Scratch (device globals; no cudaMalloc allowed)
__device__ __half g_qh [BB * HH * NN * DD];   // prescaled Q fp16, [bh][n][d]
__device__ __half g_kh [BB * HH * NN * DD];   // K fp16, [bh][n][d]
__device__ __half g_vh [BB * HH * NN * DD];   // V fp16, [bh][n][d]
__device__ __half g_oh [BB * NN * HH * DD];   // O fp16, [b*n][h*d]
__device__ __half g_wpth[OUTC * HH * DD];     // Wp^T fp16, [out][k]

// ==================== helpers ====================
__device__ __forceinline__ uint32_t smem_u32(const void* p) {
    uint32_t a;
    asm("{ .reg .u64 t; cvta.to.shared.u64 t, %1; cvt.u32.u64 %0, t; }" : "=r"(a) : "l"(p));
    return a;
}
__device__ __forceinline__ void cp16(uint32_t dst, const void* src) {
    asm volatile("cp.async.cg.shared.global [%0], [%1], 16;" :: "r"(dst), "l"(src) : "memory");
}
#define CP_COMMIT asm volatile("cp.async.commit_group;" ::: "memory")
#define CP_WAIT(n) asm volatile("cp.async.wait_group %0;" :: "n"(n) : "memory")

#define LDSM4(r, a) \
    asm volatile("ldmatrix.sync.aligned.m8n8.x4.shared.b16 {%0,%1,%2,%3}, [%4];" \
        : "=r"((r)[0]), "=r"((r)[1]), "=r"((r)[2]), "=r"((r)[3]) : "r"(a))
#define LDSM4T(r, a) \
    asm volatile("ldmatrix.sync.aligned.m8n8.x4.trans.shared.b16 {%0,%1,%2,%3}, [%4];" \
        : "=r"((r)[0]), "=r"((r)[1]), "=r"((r)[2]), "=r"((r)[3]) : "r"(a))
#define LDSM2T(r0, r1, a) \
    asm volatile("ldmatrix.sync.aligned.m8n8.x2.trans.shared.b16 {%0,%1}, [%2];" \
        : "=r"(r0), "=r"(r1) : "r"(a))

__device__ __forceinline__ void hmma(float* c, const uint32_t* a, uint32_t b0, uint32_t b1) {
    asm volatile(
        "mma.sync.aligned.m16n8k16.row.col.f32.f16.f16.f32 "
        "{%0,%1,%2,%3}, {%4,%5,%6,%7}, {%8,%9}, {%0,%1,%2,%3};"
        : "+f"(c[0]), "+f"(c[1]), "+f"(c[2]), "+f"(c[3])
        : "r"(a[0]), "r"(a[1]), "r"(a[2]), "r"(a[3]), "r"(b0), "r"(b1));
}
__device__ __forceinline__ uint32_t pack_h2(float x, float y) {
    __half2 h = __floats2half2_rn(x, y);
    return *(uint32_t*)&h;
}
// exp2 of a packed half2 on the MUFU pipe
__device__ __forceinline__ uint32_t hex2(uint32_t x) {
    uint32_t y;
    asm("ex2.approx.f16x2 %0, %1;" : "=r"(y) : "r"(x));
    return y;
}

// ==================== Kernel 1: QKV projection (HMMA fp16 hi/lo 3-pass) ====================
// grid (32, 32), 128 threads, 64 rows/CTA, 3 CTAs/SM.
// Smem: Xh @0 (9216), Xl @9216, W[w] hi @18432+w*18432, lo @+9216. Total 73728 B.
#define QKV_XH 0
#define QKV_XL 9216
#define QKV_W  18432
#define QKV_SMEM 73728

__global__ __launch_bounds__(128, 3) void qkv_kernel(
    const float* __restrict__ x,
    const float* __restrict__ Wq, const float* __restrict__ Wk, const float* __restrict__ Wv,
    const float* __restrict__ bq, const float* __restrict__ bk, const float* __restrict__ bv,
    const float* __restrict__ Wp)
{
    extern __shared__ char smc[];
    const uint32_t sb = smem_u32(smc);
    const int tid  = threadIdx.x;
    const int warp = tid >> 5, lane = tid & 31;
    const int gid  = lane >> 2, tq = lane & 3;
    const int bh = blockIdx.y;
    const int b  = bh >> 2, h = bh & 3;
    const int r0 = blockIdx.x * 64;

    // folded wp_prep: first 256 CTAs transpose one Wp row each
    {
        int bid = blockIdx.y * 32 + blockIdx.x;
        if (bid < 256) {
            g_wpth[bid * 256 + tid]       = __float2half_rn(Wp[tid * 256 + bid]);
            g_wpth[bid * 256 + tid + 128] = __float2half_rn(Wp[(tid + 128) * 256 + bid]);
        }
    }

    // stage X tile [64 rows][64 d] fp32 -> fp16 hi/lo smem (rows 144 B)
    for (int i = tid; i < 64 * 32; i += 128) {
        int r = i >> 5, c2 = i & 31;
        float2 v = *(const float2*)(x + (size_t)(b * NN + r0 + r) * 256 + h * 64 + c2 * 2);
        __half2 hh = __floats2half2_rn(v.x, v.y);
        float lx = v.x - __half2float(__low2half(hh));
        float ly = v.y - __half2float(__high2half(hh));
        uint32_t off = (uint32_t)(r * 144 + c2 * 4);
        *(uint32_t*)(smc + QKV_XH + off) = *(uint32_t*)&hh;
        *(uint32_t*)(smc + QKV_XL + off) = pack_h2(lx, ly);
    }
    // stage ALL three W^T hi/lo up front (overlapped LDGs)
    #pragma unroll
    for (int w = 0; w < 3; ++w) {
        const float* Wsrc = (w == 0) ? Wq : (w == 1) ? Wk : Wv;
        char* wbase = smc + QKV_W + w * 18432;
        for (int i = tid; i < 4096; i += 128) {
            int d = i >> 6, e = i & 63;
            float wv = Wsrc[h * 4096 + i];
            __half whi = __float2half_rn(wv);
            *(__half*)(wbase + (e * 72 + d) * 2) = whi;
            *(__half*)(wbase + 9216 + (e * 72 + d) * 2) = __float2half_rn(wv - __half2float(whi));
        }
    }
    __syncthreads();

    const uint32_t aoff = (uint32_t)((lane & 15) * 144 + ((lane & 16) ? 16 : 0));
    const uint32_t boff = (uint32_t)(((lane & 7) + ((lane & 16) ? 8 : 0)) * 144 + ((lane & 8) ? 16 : 0));
    const int row0 = r0 + warp * 16 + gid;

    #pragma unroll
    for (int w = 0; w < 3; ++w) {
        const float* bias = (w == 0) ? bq : (w == 1) ? bk : bv;
        __half* dst = (w == 0) ? g_qh : (w == 1) ? g_kh : g_vh;
        const uint32_t wb = sb + QKV_W + w * 18432;

        float acc[8][4];
        #pragma unroll
        for (int i = 0; i < 8; i++)
            #pragma unroll
            for (int j = 0; j < 4; j++) acc[i][j] = 0.0f;

        #pragma unroll
        for (int kk = 0; kk < 4; kk++) {
            uint32_t ah[4], al[4];
            LDSM4(ah, sb + QKV_XH + warp * 16 * 144 + kk * 32 + aoff);
            LDSM4(al, sb + QKV_XL + warp * 16 * 144 + kk * 32 + aoff);
            #pragma unroll
            for (int p = 0; p < 4; p++) {
                uint32_t bh4[4], bl4[4];
                LDSM4(bh4, wb + p * 16 * 144 + kk * 32 + boff);
                LDSM4(bl4, wb + 9216 + p * 16 * 144 + kk * 32 + boff);
                hmma(acc[2 * p],     ah, bh4[0], bh4[1]);
                hmma(acc[2 * p],     al, bh4[0], bh4[1]);
                hmma(acc[2 * p],     ah, bl4[0], bl4[1]);
                hmma(acc[2 * p + 1], ah, bh4[2], bh4[3]);
                hmma(acc[2 * p + 1], al, bh4[2], bh4[3]);
                hmma(acc[2 * p + 1], ah, bl4[2], bl4[3]);
            }
        }

        const float qscale = (w == 0) ? SCALE_LOG2E : 1.0f;
        size_t rb0 = ((size_t)bh * NN + row0) * 64;
        size_t rb1 = rb0 + 8 * 64;
        #pragma unroll
        for (int nd = 0; nd < 8; nd++) {
            int c = nd * 8 + tq * 2;
            float b0 = bias[h * 64 + c], b1 = bias[h * 64 + c + 1];
            *(uint32_t*)&dst[rb0 + c] =
                pack_h2((acc[nd][0] + b0) * qscale, (acc[nd][1] + b1) * qscale);
            *(uint32_t*)&dst[rb1 + c] =
                pack_h2((acc[nd][2] + b0) * qscale, (acc[nd][3] + b1) * qscale);
        }
    }
}

// ==================== Kernel 2: HMMA fp16 flash attention ====================
// grid (16, 32), 128 threads = 4 warps; warp w owns rows w*32..w*32+31, all keys.
// 3 CTAs/SM. Per-16-key-block interleaved S->exp->PV; rowsums via ones-column.
#define TILE_B   9216
#define BUF_B    18432
#define ATTN_SMEM (2 * BUF_B)

__device__ __forceinline__ void stage_tiles(uint32_t base, int kc0, int tid,
    const __half* kh, const __half* vh)
{
    for (int i = tid; i < 512; i += 128) {
        int r = i >> 3, c = i & 7;
        uint32_t d0 = base + r * 144 + c * 16;
        cp16(d0,          kh + (size_t)(kc0 + r) * 64 + c * 8);
        cp16(d0 + TILE_B, vh + (size_t)(kc0 + r) * 64 + c * 8);
    }
}

__global__ __launch_bounds__(128, 3) void attn_kernel()
{
    extern __shared__ char smc[];
    const uint32_t sb = smem_u32(smc);
    const int tid  = threadIdx.x;
    const int warp = tid >> 5, lane = tid & 31;
    const int gid  = lane >> 2, tq = lane & 3;
    const int bh = blockIdx.y;
    const int b  = bh >> 2, h = bh & 3;
    const int q0 = blockIdx.x * 128;

    const __half* qh = g_qh + (size_t)bh * NN * 64;
    const __half* kh = g_kh + (size_t)bh * NN * 64;
    const __half* vh = g_vh + (size_t)bh * NN * 64;

    stage_tiles(sb, 0, tid, kh, vh);
    CP_COMMIT;

    // ones-column init: V padding halves 64..71 <- {1.0, 0...}, both buffers
    {
        int buf = tid >> 6, r = tid & 63;
        uint4 v = make_uint4(0x00003C00u, 0u, 0u, 0u);
        *(uint4*)(smc + buf * BUF_B + TILE_B + r * 144 + 128) = v;
    }

    // Q a-frags: 2 m16 tiles (rows warp*32 + mi*16 + {gid, gid+8})
    const int rbase = q0 + warp * 32 + gid;
    uint32_t qa[4][2][4];
    #pragma unroll
    for (int kk = 0; kk < 4; kk++)
        #pragma unroll
        for (int mi = 0; mi < 2; mi++) {
            const __half* qrow = qh + (size_t)(rbase + mi * 16) * 64 + kk * 16 + tq * 2;
            qa[kk][mi][0] = *(const uint32_t*)(qrow);
            qa[kk][mi][1] = *(const uint32_t*)(qrow + 8 * 64);
            qa[kk][mi][2] = *(const uint32_t*)(qrow + 8);
            qa[kk][mi][3] = *(const uint32_t*)(qrow + 8 * 64 + 8);
        }

    float oacc[2][8][4];
    #pragma unroll
    for (int mi = 0; mi < 2; mi++)
        #pragma unroll
        for (int i = 0; i < 8; i++)
            #pragma unroll
            for (int j = 0; j < 4; j++) oacc[mi][i][j] = 0.0f;
    float rsacc[2][4];
    #pragma unroll
    for (int mi = 0; mi < 2; mi++)
        #pragma unroll
        for (int j = 0; j < 4; j++) rsacc[mi][j] = 0.0f;

    const uint32_t koff =
        (uint32_t)(((lane & 7) + ((lane & 16) ? 8 : 0)) * 144 + ((lane & 8) ? 16 : 0));
    const uint32_t voff =
        (uint32_t)((lane & 15) * 144 + ((lane & 16) ? 16 : 0));
    const uint32_t ooff = (uint32_t)((lane & 15) * 144 + 128);   // ones column

    for (int kt = 0; kt < NN / 64; ++kt) {
        __syncthreads();
        if (kt + 1 < NN / 64) {
            stage_tiles(sb + ((kt + 1) & 1) * BUF_B, (kt + 1) * 64, tid, kh, vh);
            CP_COMMIT;
            CP_WAIT(1);
        } else {
            CP_WAIT(0);
        }
        __syncthreads();
        const uint32_t kbase = sb + (kt & 1) * BUF_B;

        // ---- per 16-key block: S -> exp (f16x2 MUFU) -> PV + rowsum ----
        #pragma unroll
        for (int p = 0; p < 4; p++) {
            float sacc[2][2][4];
            #pragma unroll
            for (int mi = 0; mi < 2; mi++)
                #pragma unroll
                for (int i = 0; i < 2; i++)
                    #pragma unroll
                    for (int j = 0; j < 4; j++) sacc[mi][i][j] = 0.0f;

            #pragma unroll
            for (int kk = 0; kk < 4; kk++) {
                uint32_t bb[4];
                LDSM4(bb, kbase + p * 16 * 144 + kk * 32 + koff);
                #pragma unroll
                for (int mi = 0; mi < 2; mi++) {
                    hmma(sacc[mi][0], qa[kk][mi], bb[0], bb[1]);
                    hmma(sacc[mi][1], qa[kk][mi], bb[2], bb[3]);
                }
            }

            // exp: pack S to half2, ex2.approx.f16x2 -> P a-frags (m16k16)
            uint32_t pa[2][4];
            #pragma unroll
            for (int mi = 0; mi < 2; mi++) {
                pa[mi][0] = hex2(pack_h2(sacc[mi][0][0], sacc[mi][0][1]));
                pa[mi][1] = hex2(pack_h2(sacc[mi][0][2], sacc[mi][0][3]));
                pa[mi][2] = hex2(pack_h2(sacc[mi][1][0], sacc[mi][1][1]));
                pa[mi][3] = hex2(pack_h2(sacc[mi][1][2], sacc[mi][1][3]));
            }

            // PV over this block's 16 keys
            #pragma unroll
            for (int ndp = 0; ndp < 4; ndp++) {
                uint32_t bb[4];
                LDSM4T(bb, kbase + TILE_B + p * 16 * 144 + ndp * 32 + voff);
                #pragma unroll
                for (int mi = 0; mi < 2; mi++) {
                    hmma(oacc[mi][2 * ndp],     pa[mi], bb[0], bb[1]);
                    hmma(oacc[mi][2 * ndp + 1], pa[mi], bb[2], bb[3]);
                }
            }
            // rowsum via ones column (exact fp32 sum of fp16 P)
            {
                uint32_t o0, o1;
                LDSM2T(o0, o1, kbase + TILE_B + p * 16 * 144 + ooff);
                hmma(rsacc[0], pa[0], o0, o1);
                hmma(rsacc[1], pa[1], o0, o1);
            }
        }
    }

    // ---- normalize and write O fp16 (rowsum in col 0 -> tq==0 lanes) ----
    #pragma unroll
    for (int mi = 0; mi < 2; mi++) {
        float rsum0 = __shfl_sync(0xffffffffu, rsacc[mi][0], lane & 28);
        float rsum1 = __shfl_sync(0xffffffffu, rsacc[mi][2], lane & 28);
        const float inv0 = 1.0f / rsum0;
        const float inv1 = 1.0f / rsum1;
        size_t ob0 = ((size_t)(b * NN + rbase + mi * 16)) * 256 + h * 64;
        size_t ob1 = ob0 + (size_t)8 * 256;
        #pragma unroll
        for (int nd = 0; nd < 8; nd++) {
            int c = nd * 8 + tq * 2;
            *(uint32_t*)&g_oh[ob0 + c] =
                pack_h2(oacc[mi][nd][0] * inv0, oacc[mi][nd][1] * inv0);
            *(uint32_t*)&g_oh[ob1 + c] =
                pack_h2(oacc[mi][nd][2] * inv1, oacc[mi][nd][3] * inv1);
        }
    }
}

// ==================== Kernel 3: output projection (HMMA fp16 single-pass, double-buffered) ====================
// grid (128, 4), 256 threads. Per-stage (27648 B): A @0 [128][72], W @18432 [64][72].
#define PST 27648
#define PROJ_SMEM (2 * PST)

__device__ __forceinline__ void stage_proj(char* smcb, int r0, int c0, int kb, int tid)
{
    uint32_t base = smem_u32(smcb);
    for (int i = tid; i < 1024; i += 256) {
        int r = i >> 3, c = i & 7;
        cp16(base + r * 144 + c * 16,
             g_oh + ((size_t)(r0 + r)) * 256 + kb * 64 + c * 8);
    }
    for (int i = tid; i < 512; i += 256) {
        int r = i >> 3, c = i & 7;
        cp16(base + 18432 + r * 144 + c * 16,
             g_wpth + ((size_t)(c0 + r)) * 256 + kb * 64 + c * 8);
    }
}

__global__ __launch_bounds__(256) void proj_kernel(
    const float* __restrict__ bp, float* __restrict__ out)
{
    extern __shared__ char smc[];
    const uint32_t sb = smem_u32(smc);
    const int tid  = threadIdx.x;
    const int warp = tid >> 5, lane = tid & 31;
    const int gid  = lane >> 2, tq = lane & 3;
    const int r0 = blockIdx.x * 128;
    const int c0 = blockIdx.y * 64;

    float acc[8][4];
    #pragma unroll
    for (int i = 0; i < 8; i++)
        #pragma unroll
        for (int j = 0; j < 4; j++) acc[i][j] = 0.0f;

    const uint32_t afoff =
        (uint32_t)((lane & 15) * 144 + ((lane & 16) ? 16 : 0));
    const uint32_t bfoff =
        (uint32_t)(((lane & 7) + ((lane & 16) ? 8 : 0)) * 144 + ((lane & 8) ? 16 : 0));

    stage_proj(smc, r0, c0, 0, tid);
    CP_COMMIT;

    for (int kb = 0; kb < 4; kb++) {
        if (kb + 1 < 4) {
            stage_proj(smc + ((kb + 1) & 1) * PST, r0, c0, kb + 1, tid);
            CP_COMMIT;
            CP_WAIT(1);
        } else {
            CP_WAIT(0);
        }
        __syncthreads();
        const uint32_t kbase = sb + (kb & 1) * PST;

        #pragma unroll
        for (int kk = 0; kk < 4; kk++) {
            uint32_t ah[4];
            LDSM4(ah, kbase + warp * 16 * 144 + kk * 32 + afoff);
            #pragma unroll
            for (int p = 0; p < 4; p++) {
                uint32_t bh4[4];
                LDSM4(bh4, kbase + 18432 + p * 16 * 144 + kk * 32 + bfoff);
                hmma(acc[2 * p],     ah, bh4[0], bh4[1]);
                hmma(acc[2 * p + 1], ah, bh4[2], bh4[3]);
            }
        }
        __syncthreads();   // done reading buffer (kb&1) before it is restaged
    }

    const int m0 = r0 + warp * 16 + gid;
    #pragma unroll
    for (int nd = 0; nd < 8; nd++) {
        int cc = c0 + nd * 8 + tq * 2;
        float b0 = bp[cc], b1 = bp[cc + 1];
        *(float2*)&out[(size_t)m0 * 256 + cc] =
            make_float2(acc[nd][0] + b0, acc[nd][1] + b1);
        *(float2*)&out[(size_t)(m0 + 8) * 256 + cc] =
            make_float2(acc[nd][2] + b0, acc[nd][3] + b1);
    }
}

// ==================== launch ====================
extern "C" void kernel_launch(void* const* d_in, const int* in_sizes, int n_in,
                              void* d_out, int out_size)
{
    (void)in_sizes; (void)n_in; (void)out_size;
    const float* x  = (const float*)d_in[0];
    const float* Wq = (const float*)d_in[1];
    const float* Wk = (const float*)d_in[2];
    const float* Wv = (const float*)d_in[3];
    const float* bq = (const float*)d_in[4];
    const float* bk = (const float*)d_in[5];
    const float* bv = (const float*)d_in[6];
    const float* Wp = (const float*)d_in[7];
    const float* bp = (const float*)d_in[8];
    float* out = (float*)d_out;

    cudaFuncSetAttribute(qkv_kernel,  cudaFuncAttributeMaxDynamicSharedMemorySize, QKV_SMEM);
    cudaFuncSetAttribute(attn_kernel, cudaFuncAttributeMaxDynamicSharedMemorySize, ATTN_SMEM);
    cudaFuncSetAttribute(proj_kernel, cudaFuncAttributeMaxDynamicSharedMemorySize, PROJ_SMEM);

    qkv_kernel<<<dim3(NN / 64, BB * HH), 128, QKV_SMEM>>>(x, Wq, Wk, Wv, bq, bk, bv, Wp);
    attn_kernel<<<dim3(NN / 128, BB * HH), 128, ATTN_SMEM>>>();
    proj_kernel<<<dim3((BB * NN) / 128, OUTC / 64), 256, PROJ_SMEM>>>(bp, out);
}

// round 14
// speedup vs baseline: 1.1465x; 1.1465x over previous
#include <cuda_runtime.h>
#include <cuda_fp16.h>
#include <cstdint>

// Problem constants
#define BB 8
#define NN 2048
#define HH 4
#define DD 64
#define OUTC 256

// log2(e) / sqrt(D)
#define SCALE_LOG2E (1.4426950408889634f * 0.125f)

// Scratch (device globals; no cudaMalloc allowed)
__device__ __half g_qh [BB * HH * NN * DD];   // prescaled Q fp16, [bh][n][d]
__device__ __half g_kh [BB * HH * NN * DD];   // K fp16, [bh][n][d]
__device__ __half g_vh [BB * HH * NN * DD];   // V fp16, [bh][n][d]
__device__ __half g_oh [BB * NN * HH * DD];   // O fp16, [b*n][h*d]
__device__ __half g_wpth[OUTC * HH * DD];     // Wp^T fp16, [out][k]

// ==================== helpers ====================
__device__ __forceinline__ uint32_t smem_u32(const void* p) {
    uint32_t a;
    asm("{ .reg .u64 t; cvta.to.shared.u64 t, %1; cvt.u32.u64 %0, t; }" : "=r"(a) : "l"(p));
    return a;
}
__device__ __forceinline__ void cp16(uint32_t dst, const void* src) {
    asm volatile("cp.async.cg.shared.global [%0], [%1], 16;" :: "r"(dst), "l"(src) : "memory");
}
#define CP_COMMIT asm volatile("cp.async.commit_group;" ::: "memory")
#define CP_WAIT(n) asm volatile("cp.async.wait_group %0;" :: "n"(n) : "memory")

#define LDSM4(r, a) \
    asm volatile("ldmatrix.sync.aligned.m8n8.x4.shared.b16 {%0,%1,%2,%3}, [%4];" \
        : "=r"((r)[0]), "=r"((r)[1]), "=r"((r)[2]), "=r"((r)[3]) : "r"(a))
#define LDSM4T(r, a) \
    asm volatile("ldmatrix.sync.aligned.m8n8.x4.trans.shared.b16 {%0,%1,%2,%3}, [%4];" \
        : "=r"((r)[0]), "=r"((r)[1]), "=r"((r)[2]), "=r"((r)[3]) : "r"(a))
#define LDSM2T(r0, r1, a) \
    asm volatile("ldmatrix.sync.aligned.m8n8.x2.trans.shared.b16 {%0,%1}, [%2];" \
        : "=r"(r0), "=r"(r1) : "r"(a))

__device__ __forceinline__ void hmma(float* c, const uint32_t* a, uint32_t b0, uint32_t b1) {
    asm volatile(
        "mma.sync.aligned.m16n8k16.row.col.f32.f16.f16.f32 "
        "{%0,%1,%2,%3}, {%4,%5,%6,%7}, {%8,%9}, {%0,%1,%2,%3};"
        : "+f"(c[0]), "+f"(c[1]), "+f"(c[2]), "+f"(c[3])
        : "r"(a[0]), "r"(a[1]), "r"(a[2]), "r"(a[3]), "r"(b0), "r"(b1));
}
__device__ __forceinline__ uint32_t pack_h2(float x, float y) {
    __half2 h = __floats2half2_rn(x, y);
    return *(uint32_t*)&h;
}
// exp2 of a packed half2 on the MUFU pipe
__device__ __forceinline__ uint32_t hex2(uint32_t x) {
    uint32_t y;
    asm("ex2.approx.f16x2 %0, %1;" : "=r"(y) : "r"(x));
    return y;
}

// ==================== Kernel 1: QKV projection (persistent, pipelined) ====================
// grid (4, 32) = 128 CTAs (single wave), 256 threads. Each CTA: W staged once,
// then 4 tiles of 128 rows, double-buffered fp32 X via cp.async -> convert -> MMA.
// Smem: W[w] hi/lo @ w*18432 (55296), Xf32 dbuf @55296 (2*32768),
//       Xh/Xl dbuf @120832 (2*36864: hi 18432 + lo 18432 per buffer). Total 194560.
#define QKV_W    0
#define QKV_XF   55296
#define QKV_XHL  120832
#define QKV_XBUF 36864
#define QKV_XLO  18432
#define QKV_SMEM 194560

__global__ __launch_bounds__(256) void qkv_kernel(
    const float* __restrict__ x,
    const float* __restrict__ Wq, const float* __restrict__ Wk, const float* __restrict__ Wv,
    const float* __restrict__ bq, const float* __restrict__ bk, const float* __restrict__ bv,
    const float* __restrict__ Wp)
{
    extern __shared__ char smc[];
    const uint32_t sb = smem_u32(smc);
    const int tid  = threadIdx.x;
    const int warp = tid >> 5, lane = tid & 31;
    const int gid  = lane >> 2, tq = lane & 3;
    const int bh = blockIdx.y;
    const int b  = bh >> 2, h = bh & 3;
    const int r0 = blockIdx.x * 512;

    // folded Wp transpose: 128 CTAs x 2 rows of Wp^T each
    {
        int bid = blockIdx.y * 4 + blockIdx.x;   // 0..127
        g_wpth[(2 * bid) * 256 + tid]     = __float2half_rn(Wp[tid * 256 + 2 * bid]);
        g_wpth[(2 * bid + 1) * 256 + tid] = __float2half_rn(Wp[tid * 256 + 2 * bid + 1]);
    }

    // prefetch fp32 X tile 0 via cp.async
    for (int i = tid; i < 2048; i += 256) {
        int r = i >> 4, c4 = i & 15;
        cp16(sb + QKV_XF + r * 256 + c4 * 16,
             x + (size_t)(b * NN + r0 + r) * 256 + h * 64 + c4 * 4);
    }
    CP_COMMIT;

    // stage ALL three W^T hi/lo once
    #pragma unroll
    for (int w = 0; w < 3; ++w) {
        const float* Wsrc = (w == 0) ? Wq : (w == 1) ? Wk : Wv;
        char* wbase = smc + QKV_W + w * 18432;
        for (int i = tid; i < 4096; i += 256) {
            int d = i >> 6, e = i & 63;
            float wv = Wsrc[h * 4096 + i];
            __half whi = __float2half_rn(wv);
            *(__half*)(wbase + (e * 72 + d) * 2) = whi;
            *(__half*)(wbase + 9216 + (e * 72 + d) * 2) = __float2half_rn(wv - __half2float(whi));
        }
    }

    const uint32_t aoff = (uint32_t)((lane & 15) * 144 + ((lane & 16) ? 16 : 0));
    const uint32_t boff = (uint32_t)(((lane & 7) + ((lane & 16) ? 8 : 0)) * 144 + ((lane & 8) ? 16 : 0));

    for (int t = 0; t < 4; ++t) {
        const int rt0 = r0 + t * 128;
        // prefetch next fp32 tile
        if (t + 1 < 4) {
            for (int i = tid; i < 2048; i += 256) {
                int r = i >> 4, c4 = i & 15;
                cp16(sb + QKV_XF + ((t + 1) & 1) * 32768 + r * 256 + c4 * 16,
                     x + (size_t)(b * NN + rt0 + 128 + r) * 256 + h * 64 + c4 * 4);
            }
            CP_COMMIT;
            CP_WAIT(1);
        } else {
            CP_WAIT(0);
        }
        __syncthreads();

        // convert fp32 tile -> fp16 hi/lo (padded rows 144 B)
        {
            const char* xf = smc + QKV_XF + (t & 1) * 32768;
            char* xh = smc + QKV_XHL + (t & 1) * QKV_XBUF;
            for (int i = tid; i < 2048; i += 256) {
                int r = i >> 4, c4 = i & 15;
                float4 v = *(const float4*)(xf + r * 256 + c4 * 16);
                __half2 h0 = __floats2half2_rn(v.x, v.y);
                __half2 h1 = __floats2half2_rn(v.z, v.w);
                uint32_t l0 = pack_h2(v.x - __half2float(__low2half(h0)),
                                      v.y - __half2float(__high2half(h0)));
                uint32_t l1 = pack_h2(v.z - __half2float(__low2half(h1)),
                                      v.w - __half2float(__high2half(h1)));
                uint32_t off = (uint32_t)(r * 144 + c4 * 8);
                *(uint2*)(xh + off)           = make_uint2(*(uint32_t*)&h0, *(uint32_t*)&h1);
                *(uint2*)(xh + QKV_XLO + off) = make_uint2(l0, l1);
            }
        }
        __syncthreads();

        const uint32_t xb = sb + QKV_XHL + (t & 1) * QKV_XBUF;
        const int row0 = rt0 + warp * 16 + gid;

        #pragma unroll
        for (int w = 0; w < 3; ++w) {
            const float* bias = (w == 0) ? bq : (w == 1) ? bk : bv;
            __half* dst = (w == 0) ? g_qh : (w == 1) ? g_kh : g_vh;
            const uint32_t wb = sb + QKV_W + w * 18432;

            float acc[8][4];
            #pragma unroll
            for (int i = 0; i < 8; i++)
                #pragma unroll
                for (int j = 0; j < 4; j++) acc[i][j] = 0.0f;

            #pragma unroll
            for (int kk = 0; kk < 4; kk++) {
                uint32_t ah[4], al[4];
                LDSM4(ah, xb + warp * 16 * 144 + kk * 32 + aoff);
                LDSM4(al, xb + QKV_XLO + warp * 16 * 144 + kk * 32 + aoff);
                #pragma unroll
                for (int p = 0; p < 4; p++) {
                    uint32_t bh4[4], bl4[4];
                    LDSM4(bh4, wb + p * 16 * 144 + kk * 32 + boff);
                    LDSM4(bl4, wb + 9216 + p * 16 * 144 + kk * 32 + boff);
                    hmma(acc[2 * p],     ah, bh4[0], bh4[1]);
                    hmma(acc[2 * p],     al, bh4[0], bh4[1]);
                    hmma(acc[2 * p],     ah, bl4[0], bl4[1]);
                    hmma(acc[2 * p + 1], ah, bh4[2], bh4[3]);
                    hmma(acc[2 * p + 1], al, bh4[2], bh4[3]);
                    hmma(acc[2 * p + 1], ah, bl4[2], bl4[3]);
                }
            }

            const float qscale = (w == 0) ? SCALE_LOG2E : 1.0f;
            size_t rb0 = ((size_t)bh * NN + row0) * 64;
            size_t rb1 = rb0 + 8 * 64;
            #pragma unroll
            for (int nd = 0; nd < 8; nd++) {
                int c = nd * 8 + tq * 2;
                float b0 = bias[h * 64 + c], b1 = bias[h * 64 + c + 1];
                *(uint32_t*)&dst[rb0 + c] =
                    pack_h2((acc[nd][0] + b0) * qscale, (acc[nd][1] + b1) * qscale);
                *(uint32_t*)&dst[rb1 + c] =
                    pack_h2((acc[nd][2] + b0) * qscale, (acc[nd][3] + b1) * qscale);
            }
        }
        __syncthreads();   // done reading fp16 buffer before it is rewritten
    }
}

// ==================== Kernel 2: HMMA fp16 flash attention ====================
// grid (16, 32), 128 threads = 4 warps; warp w owns rows w*32..w*32+31, all keys.
// 3 CTAs/SM. Per-16-key-block interleaved S->exp->PV; rowsums via ones-column.
#define TILE_B   9216
#define BUF_B    18432
#define ATTN_SMEM (2 * BUF_B)

__device__ __forceinline__ void stage_tiles(uint32_t base, int kc0, int tid,
    const __half* kh, const __half* vh)
{
    for (int i = tid; i < 512; i += 128) {
        int r = i >> 3, c = i & 7;
        uint32_t d0 = base + r * 144 + c * 16;
        cp16(d0,          kh + (size_t)(kc0 + r) * 64 + c * 8);
        cp16(d0 + TILE_B, vh + (size_t)(kc0 + r) * 64 + c * 8);
    }
}

__global__ __launch_bounds__(128, 3) void attn_kernel()
{
    extern __shared__ char smc[];
    const uint32_t sb = smem_u32(smc);
    const int tid  = threadIdx.x;
    const int warp = tid >> 5, lane = tid & 31;
    const int gid  = lane >> 2, tq = lane & 3;
    const int bh = blockIdx.y;
    const int b  = bh >> 2, h = bh & 3;
    const int q0 = blockIdx.x * 128;

    const __half* qh = g_qh + (size_t)bh * NN * 64;
    const __half* kh = g_kh + (size_t)bh * NN * 64;
    const __half* vh = g_vh + (size_t)bh * NN * 64;

    stage_tiles(sb, 0, tid, kh, vh);
    CP_COMMIT;

    // ones-column init: V padding halves 64..71 <- {1.0, 0...}, both buffers
    {
        int buf = tid >> 6, r = tid & 63;
        uint4 v = make_uint4(0x00003C00u, 0u, 0u, 0u);
        *(uint4*)(smc + buf * BUF_B + TILE_B + r * 144 + 128) = v;
    }

    // Q a-frags: 2 m16 tiles (rows warp*32 + mi*16 + {gid, gid+8})
    const int rbase = q0 + warp * 32 + gid;
    uint32_t qa[4][2][4];
    #pragma unroll
    for (int kk = 0; kk < 4; kk++)
        #pragma unroll
        for (int mi = 0; mi < 2; mi++) {
            const __half* qrow = qh + (size_t)(rbase + mi * 16) * 64 + kk * 16 + tq * 2;
            qa[kk][mi][0] = *(const uint32_t*)(qrow);
            qa[kk][mi][1] = *(const uint32_t*)(qrow + 8 * 64);
            qa[kk][mi][2] = *(const uint32_t*)(qrow + 8);
            qa[kk][mi][3] = *(const uint32_t*)(qrow + 8 * 64 + 8);
        }

    float oacc[2][8][4];
    #pragma unroll
    for (int mi = 0; mi < 2; mi++)
        #pragma unroll
        for (int i = 0; i < 8; i++)
            #pragma unroll
            for (int j = 0; j < 4; j++) oacc[mi][i][j] = 0.0f;
    float rsacc[2][4];
    #pragma unroll
    for (int mi = 0; mi < 2; mi++)
        #pragma unroll
        for (int j = 0; j < 4; j++) rsacc[mi][j] = 0.0f;

    const uint32_t koff =
        (uint32_t)(((lane & 7) + ((lane & 16) ? 8 : 0)) * 144 + ((lane & 8) ? 16 : 0));
    const uint32_t voff =
        (uint32_t)((lane & 15) * 144 + ((lane & 16) ? 16 : 0));
    const uint32_t ooff = (uint32_t)((lane & 15) * 144 + 128);   // ones column

    for (int kt = 0; kt < NN / 64; ++kt) {
        __syncthreads();
        if (kt + 1 < NN / 64) {
            stage_tiles(sb + ((kt + 1) & 1) * BUF_B, (kt + 1) * 64, tid, kh, vh);
            CP_COMMIT;
            CP_WAIT(1);
        } else {
            CP_WAIT(0);
        }
        __syncthreads();
        const uint32_t kbase = sb + (kt & 1) * BUF_B;

        // ---- per 16-key block: S -> exp (f16x2 MUFU) -> PV + rowsum ----
        #pragma unroll
        for (int p = 0; p < 4; p++) {
            float sacc[2][2][4];
            #pragma unroll
            for (int mi = 0; mi < 2; mi++)
                #pragma unroll
                for (int i = 0; i < 2; i++)
                    #pragma unroll
                    for (int j = 0; j < 4; j++) sacc[mi][i][j] = 0.0f;

            #pragma unroll
            for (int kk = 0; kk < 4; kk++) {
                uint32_t bb[4];
                LDSM4(bb, kbase + p * 16 * 144 + kk * 32 + koff);
                #pragma unroll
                for (int mi = 0; mi < 2; mi++) {
                    hmma(sacc[mi][0], qa[kk][mi], bb[0], bb[1]);
                    hmma(sacc[mi][1], qa[kk][mi], bb[2], bb[3]);
                }
            }

            // exp: pack S to half2, ex2.approx.f16x2 -> P a-frags (m16k16)
            uint32_t pa[2][4];
            #pragma unroll
            for (int mi = 0; mi < 2; mi++) {
                pa[mi][0] = hex2(pack_h2(sacc[mi][0][0], sacc[mi][0][1]));
                pa[mi][1] = hex2(pack_h2(sacc[mi][0][2], sacc[mi][0][3]));
                pa[mi][2] = hex2(pack_h2(sacc[mi][1][0], sacc[mi][1][1]));
                pa[mi][3] = hex2(pack_h2(sacc[mi][1][2], sacc[mi][1][3]));
            }

            // PV over this block's 16 keys
            #pragma unroll
            for (int ndp = 0; ndp < 4; ndp++) {
                uint32_t bb[4];
                LDSM4T(bb, kbase + TILE_B + p * 16 * 144 + ndp * 32 + voff);
                #pragma unroll
                for (int mi = 0; mi < 2; mi++) {
                    hmma(oacc[mi][2 * ndp],     pa[mi], bb[0], bb[1]);
                    hmma(oacc[mi][2 * ndp + 1], pa[mi], bb[2], bb[3]);
                }
            }
            // rowsum via ones column (exact fp32 sum of fp16 P)
            {
                uint32_t o0, o1;
                LDSM2T(o0, o1, kbase + TILE_B + p * 16 * 144 + ooff);
                hmma(rsacc[0], pa[0], o0, o1);
                hmma(rsacc[1], pa[1], o0, o1);
            }
        }
    }

    // ---- normalize and write O fp16 (rowsum in col 0 -> tq==0 lanes) ----
    #pragma unroll
    for (int mi = 0; mi < 2; mi++) {
        float rsum0 = __shfl_sync(0xffffffffu, rsacc[mi][0], lane & 28);
        float rsum1 = __shfl_sync(0xffffffffu, rsacc[mi][2], lane & 28);
        const float inv0 = 1.0f / rsum0;
        const float inv1 = 1.0f / rsum1;
        size_t ob0 = ((size_t)(b * NN + rbase + mi * 16)) * 256 + h * 64;
        size_t ob1 = ob0 + (size_t)8 * 256;
        #pragma unroll
        for (int nd = 0; nd < 8; nd++) {
            int c = nd * 8 + tq * 2;
            *(uint32_t*)&g_oh[ob0 + c] =
                pack_h2(oacc[mi][nd][0] * inv0, oacc[mi][nd][1] * inv0);
            *(uint32_t*)&g_oh[ob1 + c] =
                pack_h2(oacc[mi][nd][2] * inv1, oacc[mi][nd][3] * inv1);
        }
    }
}

// ==================== Kernel 3: output projection (HMMA fp16 single-pass, double-buffered) ====================
// grid (128, 4), 256 threads. Per-stage (27648 B): A @0 [128][72], W @18432 [64][72].
#define PST 27648
#define PROJ_SMEM (2 * PST)

__device__ __forceinline__ void stage_proj(char* smcb, int r0, int c0, int kb, int tid)
{
    uint32_t base = smem_u32(smcb);
    for (int i = tid; i < 1024; i += 256) {
        int r = i >> 3, c = i & 7;
        cp16(base + r * 144 + c * 16,
             g_oh + ((size_t)(r0 + r)) * 256 + kb * 64 + c * 8);
    }
    for (int i = tid; i < 512; i += 256) {
        int r = i >> 3, c = i & 7;
        cp16(base + 18432 + r * 144 + c * 16,
             g_wpth + ((size_t)(c0 + r)) * 256 + kb * 64 + c * 8);
    }
}

__global__ __launch_bounds__(256) void proj_kernel(
    const float* __restrict__ bp, float* __restrict__ out)
{
    extern __shared__ char smc[];
    const uint32_t sb = smem_u32(smc);
    const int tid  = threadIdx.x;
    const int warp = tid >> 5, lane = tid & 31;
    const int gid  = lane >> 2, tq = lane & 3;
    const int r0 = blockIdx.x * 128;
    const int c0 = blockIdx.y * 64;

    float acc[8][4];
    #pragma unroll
    for (int i = 0; i < 8; i++)
        #pragma unroll
        for (int j = 0; j < 4; j++) acc[i][j] = 0.0f;

    const uint32_t afoff =
        (uint32_t)((lane & 15) * 144 + ((lane & 16) ? 16 : 0));
    const uint32_t bfoff =
        (uint32_t)(((lane & 7) + ((lane & 16) ? 8 : 0)) * 144 + ((lane & 8) ? 16 : 0));

    stage_proj(smc, r0, c0, 0, tid);
    CP_COMMIT;

    for (int kb = 0; kb < 4; kb++) {
        if (kb + 1 < 4) {
            stage_proj(smc + ((kb + 1) & 1) * PST, r0, c0, kb + 1, tid);
            CP_COMMIT;
            CP_WAIT(1);
        } else {
            CP_WAIT(0);
        }
        __syncthreads();
        const uint32_t kbase = sb + (kb & 1) * PST;

        #pragma unroll
        for (int kk = 0; kk < 4; kk++) {
            uint32_t ah[4];
            LDSM4(ah, kbase + warp * 16 * 144 + kk * 32 + afoff);
            #pragma unroll
            for (int p = 0; p < 4; p++) {
                uint32_t bh4[4];
                LDSM4(bh4, kbase + 18432 + p * 16 * 144 + kk * 32 + bfoff);
                hmma(acc[2 * p],     ah, bh4[0], bh4[1]);
                hmma(acc[2 * p + 1], ah, bh4[2], bh4[3]);
            }
        }
        __syncthreads();   // done reading buffer (kb&1) before it is restaged
    }

    const int m0 = r0 + warp * 16 + gid;
    #pragma unroll
    for (int nd = 0; nd < 8; nd++) {
        int cc = c0 + nd * 8 + tq * 2;
        float b0 = bp[cc], b1 = bp[cc + 1];
        *(float2*)&out[(size_t)m0 * 256 + cc] =
            make_float2(acc[nd][0] + b0, acc[nd][1] + b1);
        *(float2*)&out[(size_t)(m0 + 8) * 256 + cc] =
            make_float2(acc[nd][2] + b0, acc[nd][3] + b1);
    }
}

// ==================== launch ====================
extern "C" void kernel_launch(void* const* d_in, const int* in_sizes, int n_in,
                              void* d_out, int out_size)
{
    (void)in_sizes; (void)n_in; (void)out_size;
    const float* x  = (const float*)d_in[0];
    const float* Wq = (const float*)d_in[1];
    const float* Wk = (const float*)d_in[2];
    const float* Wv = (const float*)d_in[3];
    const float* bq = (const float*)d_in[4];
    const float* bk = (const float*)d_in[5];
    const float* bv = (const float*)d_in[6];
    const float* Wp = (const float*)d_in[7];
    const float* bp = (const float*)d_in[8];
    float* out = (float*)d_out;

    cudaFuncSetAttribute(qkv_kernel,  cudaFuncAttributeMaxDynamicSharedMemorySize, QKV_SMEM);
    cudaFuncSetAttribute(attn_kernel, cudaFuncAttributeMaxDynamicSharedMemorySize, ATTN_SMEM);
    cudaFuncSetAttribute(proj_kernel, cudaFuncAttributeMaxDynamicSharedMemorySize, PROJ_SMEM);

    qkv_kernel<<<dim3(4, BB * HH), 256, QKV_SMEM>>>(x, Wq, Wk, Wv, bq, bk, bv, Wp);
    attn_kernel<<<dim3(NN / 128, BB * HH), 128, ATTN_SMEM>>>();
    proj_kernel<<<dim3((BB * NN) / 128, OUTC / 64), 256, PROJ_SMEM>>>(bp, out);
}

// round 15
// speedup vs baseline: 1.1987x; 1.0456x over previous
#include <cuda_runtime.h>
#include <cuda_fp16.h>
#include <cstdint>

// Problem constants
#define BB 8
#define NN 2048
#define HH 4
#define DD 64
#define OUTC 256

// log2(e) / sqrt(D)
#define SCALE_LOG2E (1.4426950408889634f * 0.125f)

// Scratch (device globals; no cudaMalloc allowed)
__device__ __half g_qh [BB * HH * NN * DD];   // prescaled Q fp16, [bh][n][d]
__device__ __half g_kh [BB * HH * NN * DD];   // K fp16, [bh][n][d]
__device__ __half g_vh [BB * HH * NN * DD];   // V fp16, [bh][n][d]
__device__ __half g_oh [BB * NN * HH * DD];   // O fp16, [b*n][h*d]
__device__ __half g_wpth[OUTC * HH * DD];     // Wp^T fp16, [out][k]

// ==================== helpers ====================
__device__ __forceinline__ uint32_t smem_u32(const void* p) {
    uint32_t a;
    asm("{ .reg .u64 t; cvta.to.shared.u64 t, %1; cvt.u32.u64 %0, t; }" : "=r"(a) : "l"(p));
    return a;
}
__device__ __forceinline__ void cp16(uint32_t dst, const void* src) {
    asm volatile("cp.async.cg.shared.global [%0], [%1], 16;" :: "r"(dst), "l"(src) : "memory");
}
#define CP_COMMIT asm volatile("cp.async.commit_group;" ::: "memory")
#define CP_WAIT(n) asm volatile("cp.async.wait_group %0;" :: "n"(n) : "memory")

#define LDSM4(r, a) \
    asm volatile("ldmatrix.sync.aligned.m8n8.x4.shared.b16 {%0,%1,%2,%3}, [%4];" \
        : "=r"((r)[0]), "=r"((r)[1]), "=r"((r)[2]), "=r"((r)[3]) : "r"(a))
#define LDSM4T(r, a) \
    asm volatile("ldmatrix.sync.aligned.m8n8.x4.trans.shared.b16 {%0,%1,%2,%3}, [%4];" \
        : "=r"((r)[0]), "=r"((r)[1]), "=r"((r)[2]), "=r"((r)[3]) : "r"(a))
#define LDSM2T(r0, r1, a) \
    asm volatile("ldmatrix.sync.aligned.m8n8.x2.trans.shared.b16 {%0,%1}, [%2];" \
        : "=r"(r0), "=r"(r1) : "r"(a))

__device__ __forceinline__ void hmma(float* c, const uint32_t* a, uint32_t b0, uint32_t b1) {
    asm volatile(
        "mma.sync.aligned.m16n8k16.row.col.f32.f16.f16.f32 "
        "{%0,%1,%2,%3}, {%4,%5,%6,%7}, {%8,%9}, {%0,%1,%2,%3};"
        : "+f"(c[0]), "+f"(c[1]), "+f"(c[2]), "+f"(c[3])
        : "r"(a[0]), "r"(a[1]), "r"(a[2]), "r"(a[3]), "r"(b0), "r"(b1));
}
__device__ __forceinline__ uint32_t pack_h2(float x, float y) {
    __half2 h = __floats2half2_rn(x, y);
    return *(uint32_t*)&h;
}
// exp2 of a packed half2 on the MUFU pipe
__device__ __forceinline__ uint32_t hex2(uint32_t x) {
    uint32_t y;
    asm("ex2.approx.f16x2 %0, %1;" : "=r"(y) : "r"(x));
    return y;
}

// ==================== Kernel 1: QKV projection (persistent, pipelined, single-pass fp16) ====================
// grid (4, 32) = 128 CTAs (single wave), 256 threads. Each CTA: W staged once (hi only),
// then 4 tiles of 128 rows, double-buffered fp32 X via cp.async -> convert -> MMA.
// Smem: W[w] @ w*9216 (27648), Xf32 dbuf @27648 (2*32768), Xh dbuf @93184 (2*18432). Total 130048.
#define QKV_W    0
#define QKV_XF   27648
#define QKV_XH   93184
#define QKV_SMEM 130048

__global__ __launch_bounds__(256) void qkv_kernel(
    const float* __restrict__ x,
    const float* __restrict__ Wq, const float* __restrict__ Wk, const float* __restrict__ Wv,
    const float* __restrict__ bq, const float* __restrict__ bk, const float* __restrict__ bv,
    const float* __restrict__ Wp)
{
    extern __shared__ char smc[];
    const uint32_t sb = smem_u32(smc);
    const int tid  = threadIdx.x;
    const int warp = tid >> 5, lane = tid & 31;
    const int gid  = lane >> 2, tq = lane & 3;
    const int bh = blockIdx.y;
    const int b  = bh >> 2, h = bh & 3;
    const int r0 = blockIdx.x * 512;

    // folded Wp transpose: 128 CTAs x 2 rows of Wp^T each
    {
        int bid = blockIdx.y * 4 + blockIdx.x;   // 0..127
        g_wpth[(2 * bid) * 256 + tid]     = __float2half_rn(Wp[tid * 256 + 2 * bid]);
        g_wpth[(2 * bid + 1) * 256 + tid] = __float2half_rn(Wp[tid * 256 + 2 * bid + 1]);
    }

    // prefetch fp32 X tile 0 via cp.async
    for (int i = tid; i < 2048; i += 256) {
        int r = i >> 4, c4 = i & 15;
        cp16(sb + QKV_XF + r * 256 + c4 * 16,
             x + (size_t)(b * NN + r0 + r) * 256 + h * 64 + c4 * 4);
    }
    CP_COMMIT;

    // stage ALL three W^T (fp16, hi only) once
    #pragma unroll
    for (int w = 0; w < 3; ++w) {
        const float* Wsrc = (w == 0) ? Wq : (w == 1) ? Wk : Wv;
        char* wbase = smc + QKV_W + w * 9216;
        for (int i = tid; i < 4096; i += 256) {
            int d = i >> 6, e = i & 63;
            *(__half*)(wbase + (e * 72 + d) * 2) = __float2half_rn(Wsrc[h * 4096 + i]);
        }
    }

    const uint32_t aoff = (uint32_t)((lane & 15) * 144 + ((lane & 16) ? 16 : 0));
    const uint32_t boff = (uint32_t)(((lane & 7) + ((lane & 16) ? 8 : 0)) * 144 + ((lane & 8) ? 16 : 0));

    for (int t = 0; t < 4; ++t) {
        const int rt0 = r0 + t * 128;
        // prefetch next fp32 tile
        if (t + 1 < 4) {
            for (int i = tid; i < 2048; i += 256) {
                int r = i >> 4, c4 = i & 15;
                cp16(sb + QKV_XF + ((t + 1) & 1) * 32768 + r * 256 + c4 * 16,
                     x + (size_t)(b * NN + rt0 + 128 + r) * 256 + h * 64 + c4 * 4);
            }
            CP_COMMIT;
            CP_WAIT(1);
        } else {
            CP_WAIT(0);
        }
        __syncthreads();

        // convert fp32 tile -> fp16 (padded rows 144 B)
        {
            const char* xf = smc + QKV_XF + (t & 1) * 32768;
            char* xh = smc + QKV_XH + (t & 1) * 18432;
            for (int i = tid; i < 2048; i += 256) {
                int r = i >> 4, c4 = i & 15;
                float4 v = *(const float4*)(xf + r * 256 + c4 * 16);
                __half2 h0 = __floats2half2_rn(v.x, v.y);
                __half2 h1 = __floats2half2_rn(v.z, v.w);
                *(uint2*)(xh + r * 144 + c4 * 8) =
                    make_uint2(*(uint32_t*)&h0, *(uint32_t*)&h1);
            }
        }
        __syncthreads();

        const uint32_t xb = sb + QKV_XH + (t & 1) * 18432;
        const int row0 = rt0 + warp * 16 + gid;

        #pragma unroll
        for (int w = 0; w < 3; ++w) {
            const float* bias = (w == 0) ? bq : (w == 1) ? bk : bv;
            __half* dst = (w == 0) ? g_qh : (w == 1) ? g_kh : g_vh;
            const uint32_t wb = sb + QKV_W + w * 9216;

            float acc[8][4];
            #pragma unroll
            for (int i = 0; i < 8; i++)
                #pragma unroll
                for (int j = 0; j < 4; j++) acc[i][j] = 0.0f;

            #pragma unroll
            for (int kk = 0; kk < 4; kk++) {
                uint32_t ah[4];
                LDSM4(ah, xb + warp * 16 * 144 + kk * 32 + aoff);
                #pragma unroll
                for (int p = 0; p < 4; p++) {
                    uint32_t bh4[4];
                    LDSM4(bh4, wb + p * 16 * 144 + kk * 32 + boff);
                    hmma(acc[2 * p],     ah, bh4[0], bh4[1]);
                    hmma(acc[2 * p + 1], ah, bh4[2], bh4[3]);
                }
            }

            const float qscale = (w == 0) ? SCALE_LOG2E : 1.0f;
            size_t rb0 = ((size_t)bh * NN + row0) * 64;
            size_t rb1 = rb0 + 8 * 64;
            #pragma unroll
            for (int nd = 0; nd < 8; nd++) {
                int c = nd * 8 + tq * 2;
                float b0 = bias[h * 64 + c], b1 = bias[h * 64 + c + 1];
                *(uint32_t*)&dst[rb0 + c] =
                    pack_h2((acc[nd][0] + b0) * qscale, (acc[nd][1] + b1) * qscale);
                *(uint32_t*)&dst[rb1 + c] =
                    pack_h2((acc[nd][2] + b0) * qscale, (acc[nd][3] + b1) * qscale);
            }
        }
        __syncthreads();   // done reading fp16 buffer before it is rewritten
    }
}

// ==================== Kernel 2: HMMA fp16 flash attention ====================
// grid (16, 32), 128 threads = 4 warps; warp w owns rows w*32..w*32+31, all keys.
// 3 CTAs/SM. Per-16-key-block interleaved S->exp->PV; rowsums via ones-column.
#define TILE_B   9216
#define BUF_B    18432
#define ATTN_SMEM (2 * BUF_B)

__device__ __forceinline__ void stage_tiles(uint32_t base, int kc0, int tid,
    const __half* kh, const __half* vh)
{
    for (int i = tid; i < 512; i += 128) {
        int r = i >> 3, c = i & 7;
        uint32_t d0 = base + r * 144 + c * 16;
        cp16(d0,          kh + (size_t)(kc0 + r) * 64 + c * 8);
        cp16(d0 + TILE_B, vh + (size_t)(kc0 + r) * 64 + c * 8);
    }
}

__global__ __launch_bounds__(128, 3) void attn_kernel()
{
    extern __shared__ char smc[];
    const uint32_t sb = smem_u32(smc);
    const int tid  = threadIdx.x;
    const int warp = tid >> 5, lane = tid & 31;
    const int gid  = lane >> 2, tq = lane & 3;
    const int bh = blockIdx.y;
    const int b  = bh >> 2, h = bh & 3;
    const int q0 = blockIdx.x * 128;

    const __half* qh = g_qh + (size_t)bh * NN * 64;
    const __half* kh = g_kh + (size_t)bh * NN * 64;
    const __half* vh = g_vh + (size_t)bh * NN * 64;

    stage_tiles(sb, 0, tid, kh, vh);
    CP_COMMIT;

    // ones-column init: V padding halves 64..71 <- {1.0, 0...}, both buffers
    {
        int buf = tid >> 6, r = tid & 63;
        uint4 v = make_uint4(0x00003C00u, 0u, 0u, 0u);
        *(uint4*)(smc + buf * BUF_B + TILE_B + r * 144 + 128) = v;
    }

    // Q a-frags: 2 m16 tiles (rows warp*32 + mi*16 + {gid, gid+8})
    const int rbase = q0 + warp * 32 + gid;
    uint32_t qa[4][2][4];
    #pragma unroll
    for (int kk = 0; kk < 4; kk++)
        #pragma unroll
        for (int mi = 0; mi < 2; mi++) {
            const __half* qrow = qh + (size_t)(rbase + mi * 16) * 64 + kk * 16 + tq * 2;
            qa[kk][mi][0] = *(const uint32_t*)(qrow);
            qa[kk][mi][1] = *(const uint32_t*)(qrow + 8 * 64);
            qa[kk][mi][2] = *(const uint32_t*)(qrow + 8);
            qa[kk][mi][3] = *(const uint32_t*)(qrow + 8 * 64 + 8);
        }

    float oacc[2][8][4];
    #pragma unroll
    for (int mi = 0; mi < 2; mi++)
        #pragma unroll
        for (int i = 0; i < 8; i++)
            #pragma unroll
            for (int j = 0; j < 4; j++) oacc[mi][i][j] = 0.0f;
    float rsacc[2][4];
    #pragma unroll
    for (int mi = 0; mi < 2; mi++)
        #pragma unroll
        for (int j = 0; j < 4; j++) rsacc[mi][j] = 0.0f;

    const uint32_t koff =
        (uint32_t)(((lane & 7) + ((lane & 16) ? 8 : 0)) * 144 + ((lane & 8) ? 16 : 0));
    const uint32_t voff =
        (uint32_t)((lane & 15) * 144 + ((lane & 16) ? 16 : 0));
    const uint32_t ooff = (uint32_t)((lane & 15) * 144 + 128);   // ones column

    for (int kt = 0; kt < NN / 64; ++kt) {
        __syncthreads();
        if (kt + 1 < NN / 64) {
            stage_tiles(sb + ((kt + 1) & 1) * BUF_B, (kt + 1) * 64, tid, kh, vh);
            CP_COMMIT;
            CP_WAIT(1);
        } else {
            CP_WAIT(0);
        }
        __syncthreads();
        const uint32_t kbase = sb + (kt & 1) * BUF_B;

        // ---- per 16-key block: S -> exp (f16x2 MUFU) -> PV + rowsum ----
        #pragma unroll
        for (int p = 0; p < 4; p++) {
            float sacc[2][2][4];
            #pragma unroll
            for (int mi = 0; mi < 2; mi++)
                #pragma unroll
                for (int i = 0; i < 2; i++)
                    #pragma unroll
                    for (int j = 0; j < 4; j++) sacc[mi][i][j] = 0.0f;

            #pragma unroll
            for (int kk = 0; kk < 4; kk++) {
                uint32_t bb[4];
                LDSM4(bb, kbase + p * 16 * 144 + kk * 32 + koff);
                #pragma unroll
                for (int mi = 0; mi < 2; mi++) {
                    hmma(sacc[mi][0], qa[kk][mi], bb[0], bb[1]);
                    hmma(sacc[mi][1], qa[kk][mi], bb[2], bb[3]);
                }
            }

            // exp: pack S to half2, ex2.approx.f16x2 -> P a-frags (m16k16)
            uint32_t pa[2][4];
            #pragma unroll
            for (int mi = 0; mi < 2; mi++) {
                pa[mi][0] = hex2(pack_h2(sacc[mi][0][0], sacc[mi][0][1]));
                pa[mi][1] = hex2(pack_h2(sacc[mi][0][2], sacc[mi][0][3]));
                pa[mi][2] = hex2(pack_h2(sacc[mi][1][0], sacc[mi][1][1]));
                pa[mi][3] = hex2(pack_h2(sacc[mi][1][2], sacc[mi][1][3]));
            }

            // PV over this block's 16 keys
            #pragma unroll
            for (int ndp = 0; ndp < 4; ndp++) {
                uint32_t bb[4];
                LDSM4T(bb, kbase + TILE_B + p * 16 * 144 + ndp * 32 + voff);
                #pragma unroll
                for (int mi = 0; mi < 2; mi++) {
                    hmma(oacc[mi][2 * ndp],     pa[mi], bb[0], bb[1]);
                    hmma(oacc[mi][2 * ndp + 1], pa[mi], bb[2], bb[3]);
                }
            }
            // rowsum via ones column (exact fp32 sum of fp16 P)
            {
                uint32_t o0, o1;
                LDSM2T(o0, o1, kbase + TILE_B + p * 16 * 144 + ooff);
                hmma(rsacc[0], pa[0], o0, o1);
                hmma(rsacc[1], pa[1], o0, o1);
            }
        }
    }

    // ---- normalize and write O fp16 (rowsum in col 0 -> tq==0 lanes) ----
    #pragma unroll
    for (int mi = 0; mi < 2; mi++) {
        float rsum0 = __shfl_sync(0xffffffffu, rsacc[mi][0], lane & 28);
        float rsum1 = __shfl_sync(0xffffffffu, rsacc[mi][2], lane & 28);
        const float inv0 = 1.0f / rsum0;
        const float inv1 = 1.0f / rsum1;
        size_t ob0 = ((size_t)(b * NN + rbase + mi * 16)) * 256 + h * 64;
        size_t ob1 = ob0 + (size_t)8 * 256;
        #pragma unroll
        for (int nd = 0; nd < 8; nd++) {
            int c = nd * 8 + tq * 2;
            *(uint32_t*)&g_oh[ob0 + c] =
                pack_h2(oacc[mi][nd][0] * inv0, oacc[mi][nd][1] * inv0);
            *(uint32_t*)&g_oh[ob1 + c] =
                pack_h2(oacc[mi][nd][2] * inv1, oacc[mi][nd][3] * inv1);
        }
    }
}

// ==================== Kernel 3: output projection (HMMA fp16 single-pass, double-buffered) ====================
// grid (128, 4), 256 threads. Per-stage (27648 B): A @0 [128][72], W @18432 [64][72].
#define PST 27648
#define PROJ_SMEM (2 * PST)

__device__ __forceinline__ void stage_proj(char* smcb, int r0, int c0, int kb, int tid)
{
    uint32_t base = smem_u32(smcb);
    for (int i = tid; i < 1024; i += 256) {
        int r = i >> 3, c = i & 7;
        cp16(base + r * 144 + c * 16,
             g_oh + ((size_t)(r0 + r)) * 256 + kb * 64 + c * 8);
    }
    for (int i = tid; i < 512; i += 256) {
        int r = i >> 3, c = i & 7;
        cp16(base + 18432 + r * 144 + c * 16,
             g_wpth + ((size_t)(c0 + r)) * 256 + kb * 64 + c * 8);
    }
}

__global__ __launch_bounds__(256) void proj_kernel(
    const float* __restrict__ bp, float* __restrict__ out)
{
    extern __shared__ char smc[];
    const uint32_t sb = smem_u32(smc);
    const int tid  = threadIdx.x;
    const int warp = tid >> 5, lane = tid & 31;
    const int gid  = lane >> 2, tq = lane & 3;
    const int r0 = blockIdx.x * 128;
    const int c0 = blockIdx.y * 64;

    float acc[8][4];
    #pragma unroll
    for (int i = 0; i < 8; i++)
        #pragma unroll
        for (int j = 0; j < 4; j++) acc[i][j] = 0.0f;

    const uint32_t afoff =
        (uint32_t)((lane & 15) * 144 + ((lane & 16) ? 16 : 0));
    const uint32_t bfoff =
        (uint32_t)(((lane & 7) + ((lane & 16) ? 8 : 0)) * 144 + ((lane & 8) ? 16 : 0));

    stage_proj(smc, r0, c0, 0, tid);
    CP_COMMIT;

    for (int kb = 0; kb < 4; kb++) {
        if (kb + 1 < 4) {
            stage_proj(smc + ((kb + 1) & 1) * PST, r0, c0, kb + 1, tid);
            CP_COMMIT;
            CP_WAIT(1);
        } else {
            CP_WAIT(0);
        }
        __syncthreads();
        const uint32_t kbase = sb + (kb & 1) * PST;

        #pragma unroll
        for (int kk = 0; kk < 4; kk++) {
            uint32_t ah[4];
            LDSM4(ah, kbase + warp * 16 * 144 + kk * 32 + afoff);
            #pragma unroll
            for (int p = 0; p < 4; p++) {
                uint32_t bh4[4];
                LDSM4(bh4, kbase + 18432 + p * 16 * 144 + kk * 32 + bfoff);
                hmma(acc[2 * p],     ah, bh4[0], bh4[1]);
                hmma(acc[2 * p + 1], ah, bh4[2], bh4[3]);
            }
        }
        __syncthreads();   // done reading buffer (kb&1) before it is restaged
    }

    const int m0 = r0 + warp * 16 + gid;
    #pragma unroll
    for (int nd = 0; nd < 8; nd++) {
        int cc = c0 + nd * 8 + tq * 2;
        float b0 = bp[cc], b1 = bp[cc + 1];
        *(float2*)&out[(size_t)m0 * 256 + cc] =
            make_float2(acc[nd][0] + b0, acc[nd][1] + b1);
        *(float2*)&out[(size_t)(m0 + 8) * 256 + cc] =
            make_float2(acc[nd][2] + b0, acc[nd][3] + b1);
    }
}

// ==================== launch ====================
extern "C" void kernel_launch(void* const* d_in, const int* in_sizes, int n_in,
                              void* d_out, int out_size)
{
    (void)in_sizes; (void)n_in; (void)out_size;
    const float* x  = (const float*)d_in[0];
    const float* Wq = (const float*)d_in[1];
    const float* Wk = (const float*)d_in[2];
    const float* Wv = (const float*)d_in[3];
    const float* bq = (const float*)d_in[4];
    const float* bk = (const float*)d_in[5];
    const float* bv = (const float*)d_in[6];
    const float* Wp = (const float*)d_in[7];
    const float* bp = (const float*)d_in[8];
    float* out = (float*)d_out;

    cudaFuncSetAttribute(qkv_kernel,  cudaFuncAttributeMaxDynamicSharedMemorySize, QKV_SMEM);
    cudaFuncSetAttribute(attn_kernel, cudaFuncAttributeMaxDynamicSharedMemorySize, ATTN_SMEM);
    cudaFuncSetAttribute(proj_kernel, cudaFuncAttributeMaxDynamicSharedMemorySize, PROJ_SMEM);

    qkv_kernel<<<dim3(4, BB * HH), 256, QKV_SMEM>>>(x, Wq, Wk, Wv, bq, bk, bv, Wp);
    attn_kernel<<<dim3(NN / 128, BB * HH), 128, ATTN_SMEM>>>();
    proj_kernel<<<dim3((BB * NN) / 128, OUTC / 64), 256, PROJ_SMEM>>>(bp, out);
}